// round 12
// baseline (speedup 1.0000x reference)
#include <cuda_runtime.h>

typedef unsigned long long u64t;

__device__ __forceinline__ u64t fma2(u64t a, u64t b, u64t c) {
    u64t d;
    asm("fma.rn.f32x2 %0, %1, %2, %3;" : "=l"(d) : "l"(a), "l"(b), "l"(c));
    return d;
}
__device__ __forceinline__ u64t add2(u64t a, u64t b) {
    u64t d;
    asm("add.rn.f32x2 %0, %1, %2;" : "=l"(d) : "l"(a), "l"(b));
    return d;
}
__device__ __forceinline__ u64t pk2(float lo, float hi) {
    u64t d;
    asm("mov.b64 %0, {%1, %2};" : "=l"(d) : "f"(lo), "f"(hi));
    return d;
}
__device__ __forceinline__ void unpk(u64t v, float& lo, float& hi) {
    asm("mov.b64 {%0, %1}, %2;" : "=f"(lo), "=f"(hi) : "l"(v));
}
__device__ __forceinline__ float fsqrt_ap(float x) {
    float y;
    asm("sqrt.approx.f32 %0, %1;" : "=f"(y) : "f"(x));
    return y;
}
__device__ __forceinline__ u64t shx1(u64t v) {
    unsigned lo = (unsigned)v, hi = (unsigned)(v >> 32);
    lo = __shfl_xor_sync(0xffffffffu, lo, 1);
    hi = __shfl_xor_sync(0xffffffffu, hi, 1);
    return ((u64t)hi << 32) | lo;
}

// ---- weight region (u64t units), same packed layout as R10 ----
// x-order (new k): [rot 0..8, jtr 9..11, feat 12..17, bone 18, pad 19]
//   old-k map K(m): m<12 -> m ; 12..17 -> m+1 ; 18 -> 12 ; 19 -> zero
// sW1': [24 j][10 kp][20 r]  u64 = (W1[j][r][K(2kp)], W1[j][r][K(2kp+1)])
// sW2 : [24 j][20 k][3 dp]   (k=19 row = b2; fed by hs[9]==1 on odd lane)
// sW0': [144 kp][6 d]        u64 = (W0[d][F(2kp)], W0[d][F(2kp+1)])
// sB1': [24 j][20 r]         u64 = (b1, 0)
// sB0': [6 d]                u64 = (b0, 0)
#define OW1 0
#define OW2 4800
#define OW0 6240
#define OB1 7104
#define OB0 7584
#define SM_U64 7590            // 60720 B

// ---- stash: element-major, 292 floats/element, 128 elements ----
// f' = 12*J + i : i in [0,9) = rot i ; i in [9,12) = jtr c
#define ESTRIDE 292
#define STASH_WORDS (128 * ESTRIDE)
#define SMEM_BYTES  (SM_U64 * 8 + STASH_WORDS * 4)    // 210224 B

template<int J, int PS, int WS>
__device__ __forceinline__ void do_joint(
    float* __restrict__ seA, float* __restrict__ seB,
    int half, const u64t* __restrict__ sm,
    u64t (&fA)[4][3], u64t (&fB)[4][3],
    float (&jxA)[4], float (&jyA)[4], float (&jzA)[4],
    float (&jxB)[4], float (&jyB)[4], float (&jzB)[4],
    const u64t (&gA)[3], const u64t (&gB)[3])
{
    // 12 inputs of joint J for both elements (aligned LDS.128 blocks; own slots,
    // never written before this joint)
    u64t xpA[10], xpB[10];
    ulonglong2 qA2, qB2;
    {
        const ulonglong2* xqA = (const ulonglong2*)(seA + 12*J);
        const ulonglong2* xqB = (const ulonglong2*)(seB + 12*J);
        ulonglong2 a0 = xqA[0], a1 = xqA[1]; qA2 = xqA[2];
        ulonglong2 b0 = xqB[0], b1 = xqB[1]; qB2 = xqB[2];
        xpA[0]=a0.x; xpA[1]=a0.y; xpA[2]=a1.x; xpA[3]=a1.y; xpA[4]=qA2.x; xpA[5]=qA2.y;
        xpB[0]=b0.x; xpB[1]=b0.y; xpB[2]=b1.x; xpB[3]=b1.y; xpB[4]=qB2.x; xpB[5]=qB2.y;
    }
    float t8A, jxv_A, jyv_A, jzv_A, t8B, jxv_B, jyv_B, jzv_B;
    unpk(qA2.x, t8A, jxv_A); unpk(qA2.y, jyv_A, jzv_A);
    unpk(qB2.x, t8B, jxv_B); unpk(qB2.y, jyv_B, jzv_B);
    (void)t8A; (void)t8B;

    float boneA, boneB;
    if (PS < 0) {
        boneA = fsqrt_ap(jxv_A*jxv_A + jyv_A*jyv_A + jzv_A*jzv_A);
        boneB = fsqrt_ap(jxv_B*jxv_B + jyv_B*jyv_B + jzv_B*jzv_B);
        xpA[6] = gA[0]; xpA[7] = gA[1]; xpA[8] = gA[2];
        xpB[6] = gB[0]; xpB[7] = gB[1]; xpB[8] = gB[2];
    } else {
        const int P = (PS < 0) ? 0 : PS;
        float dxA = jxv_A - jxA[P], dyA = jyv_A - jyA[P], dzA = jzv_A - jzA[P];
        float dxB = jxv_B - jxB[P], dyB = jyv_B - jyB[P], dzB = jzv_B - jzB[P];
        boneA = fsqrt_ap(dxA*dxA + dyA*dyA + dzA*dzA);
        boneB = fsqrt_ap(dxB*dxB + dyB*dyB + dzB*dzB);
        xpA[6] = fA[P][0]; xpA[7] = fA[P][1]; xpA[8] = fA[P][2];
        xpB[6] = fB[P][0]; xpB[7] = fB[P][1]; xpB[8] = fB[P][2];
    }
    jxA[WS] = jxv_A; jyA[WS] = jyv_A; jzA[WS] = jzv_A;
    jxB[WS] = jxv_B; jyB[WS] = jyv_B; jzB[WS] = jzv_B;
    xpA[9] = pk2(boneA, boneA);      // hi weight is 0
    xpB[9] = pk2(boneB, boneB);

    // ---- layer 1: 10 rows (this half), weights loaded ONCE for both elements ----
    u64t accA[10], accB[10];
    {
        const ulonglong2* bb = (const ulonglong2*)(sm + OB1 + J*20 + 10*half);
        ulonglong2 c0 = bb[0], c1 = bb[1], c2 = bb[2], c3 = bb[3], c4 = bb[4];
        accA[0]=c0.x; accA[1]=c0.y; accA[2]=c1.x; accA[3]=c1.y; accA[4]=c2.x;
        accA[5]=c2.y; accA[6]=c3.x; accA[7]=c3.y; accA[8]=c4.x; accA[9]=c4.y;
#pragma unroll
        for (int r = 0; r < 10; ++r) accB[r] = accA[r];
    }
    const u64t* wb = sm + OW1 + (J*10)*20 + 10*half;
#pragma unroll
    for (int i = 0; i < 10; ++i) {
        const ulonglong2* wr = (const ulonglong2*)(wb + i*20);
        ulonglong2 wa = wr[0], wc = wr[1], wd = wr[2], we = wr[3], wf = wr[4];
        u64t xA = xpA[i], xB = xpB[i];
        accA[0] = fma2(xA, wa.x, accA[0]);  accB[0] = fma2(xB, wa.x, accB[0]);
        accA[1] = fma2(xA, wa.y, accA[1]);  accB[1] = fma2(xB, wa.y, accB[1]);
        accA[2] = fma2(xA, wc.x, accA[2]);  accB[2] = fma2(xB, wc.x, accB[2]);
        accA[3] = fma2(xA, wc.y, accA[3]);  accB[3] = fma2(xB, wc.y, accB[3]);
        accA[4] = fma2(xA, wd.x, accA[4]);  accB[4] = fma2(xB, wd.x, accB[4]);
        accA[5] = fma2(xA, wd.y, accA[5]);  accB[5] = fma2(xB, wd.y, accB[5]);
        accA[6] = fma2(xA, we.x, accA[6]);  accB[6] = fma2(xB, we.x, accB[6]);
        accA[7] = fma2(xA, we.y, accA[7]);  accB[7] = fma2(xB, we.y, accB[7]);
        accA[8] = fma2(xA, wf.x, accA[8]);  accB[8] = fma2(xB, wf.x, accB[8]);
        accA[9] = fma2(xA, wf.y, accA[9]);  accB[9] = fma2(xB, wf.y, accB[9]);
    }

    // combine even/odd-kp partials + relu
    float hsA[10], hsB[10];
#pragma unroll
    for (int r = 0; r < 10; ++r) {
        float a, b;
        unpk(accA[r], a, b); hsA[r] = fmaxf(a + b, 0.f);
        unpk(accB[r], a, b); hsB[r] = fmaxf(a + b, 0.f);
    }
    if (half) { hsA[9] = 1.0f; hsB[9] = 1.0f; }   // row 19 -> b2 row of sW2

    // ---- layer 2: 15 shared weight LDS.128, dual FMA bursts ----
    ulonglong2 wz[15];
    {
        const ulonglong2* wp = (const ulonglong2*)(sm + OW2 + (J*20 + 10*half)*3);
#pragma unroll
        for (int i = 0; i < 15; ++i) wz[i] = wp[i];
    }
    u64t oA0 = 0ull, oA1 = 0ull, oA2 = 0ull;
    u64t oB0 = 0ull, oB1 = 0ull, oB2 = 0ull;
#pragma unroll
    for (int i = 0; i < 5; ++i) {
        u64t xA0 = pk2(hsA[2*i],   hsA[2*i]);
        u64t xA1 = pk2(hsA[2*i+1], hsA[2*i+1]);
        u64t xB0 = pk2(hsB[2*i],   hsB[2*i]);
        u64t xB1 = pk2(hsB[2*i+1], hsB[2*i+1]);
        oA0 = fma2(xA0, wz[3*i  ].x, oA0);  oB0 = fma2(xB0, wz[3*i  ].x, oB0);
        oA1 = fma2(xA0, wz[3*i  ].y, oA1);  oB1 = fma2(xB0, wz[3*i  ].y, oB1);
        oA2 = fma2(xA0, wz[3*i+1].x, oA2);  oB2 = fma2(xB0, wz[3*i+1].x, oB2);
        oA0 = fma2(xA1, wz[3*i+1].y, oA0);  oB0 = fma2(xB1, wz[3*i+1].y, oB0);
        oA1 = fma2(xA1, wz[3*i+2].x, oA1);  oB1 = fma2(xB1, wz[3*i+2].x, oB1);
        oA2 = fma2(xA1, wz[3*i+2].y, oA2);  oB2 = fma2(xB1, wz[3*i+2].y, oB2);
    }
    oA0 = add2(oA0, shx1(oA0));
    oA1 = add2(oA1, shx1(oA1));
    oA2 = add2(oA2, shx1(oA2));
    oB0 = add2(oB0, shx1(oB0));
    oB1 = add2(oB1, shx1(oB1));
    oB2 = add2(oB2, shx1(oB2));

    // keep in registers for children
    fA[WS][0] = oA0; fA[WS][1] = oA1; fA[WS][2] = oA2;
    fB[WS][0] = oB0; fB[WS][1] = oB1; fB[WS][2] = oB2;

    // stash stores are for the EPILOGUE only (read after __syncthreads)
    if (half == 0) {
        u64t* d = (u64t*)(seA + 12*J);
        d[0] = oA0; d[1] = oA1; d[2] = oA2;
    } else {
        u64t* d = (u64t*)(seB + 12*J);
        d[0] = oB0; d[1] = oB1; d[2] = oB2;
    }
}

__global__ void __launch_bounds__(128, 1)
pose_kernel(const float* __restrict__ rots, const float* __restrict__ jtrs,
            const float* __restrict__ W0, const float* __restrict__ b0,
            const float* __restrict__ W1, const float* __restrict__ b1,
            const float* __restrict__ W2, const float* __restrict__ b2,
            float* __restrict__ out)
{
    extern __shared__ u64t sm[];
    float* stash = (float*)(sm + SM_U64);
    const int tid = threadIdx.x;

    // ---- staging: coalesced LDG.128 -> contiguous STS (f' interleaved layout) ----
    {
        const float4* gr4 = (const float4*)(rots + (size_t)blockIdx.x * 128 * 216);
        const float4* gt4 = (const float4*)(jtrs + (size_t)blockIdx.x * 128 * 72);
#pragma unroll 6
        for (int i = 0; i < 54; ++i) {                  // rots: 6912 float4
            int G = i*128 + tid;
            float4 v = gr4[G];
            int e = G / 54, f4 = G % 54;
            float* dst = stash + e*ESTRIDE;
            int fo = 4*f4;
            float vv[4] = {v.x, v.y, v.z, v.w};
#pragma unroll
            for (int c = 0; c < 4; ++c) {
                int f = fo + c;
                int Jc = f / 9;                         // f' = f + 3*Jc
                dst[f + 3*Jc] = vv[c];
            }
        }
#pragma unroll 6
        for (int i = 0; i < 18; ++i) {                  // jtrs: 2304 float4
            int G = i*128 + tid;
            float4 v = gt4[G];
            int e = G / 18, f4 = G % 18;
            float* dst = stash + e*ESTRIDE;
            int mo = 4*f4;
            float vv[4] = {v.x, v.y, v.z, v.w};
#pragma unroll
            for (int c = 0; c < 4; ++c) {
                int m = mo + c;
                int Jt = m / 3;                         // f' = m + 9*Jt + 9
                dst[m + 9*Jt + 9] = vv[c];
            }
        }
    }

    // ---- weight packing (identical layout to R10) ----
    for (int idx = tid; idx < 24*10*20; idx += 128) {   // sW1' [j][kp][20 r]
        int r = idx % 20; int t = idx / 20; int i = t % 10; int j = t / 10;
        int m0 = 2*i, m1 = 2*i + 1;
        float lo = 0.f, hi = 0.f;
        if (r < 19) {
            int k0 = (m0 < 12) ? m0 : (m0 < 18 ? m0 + 1 : 12);
            lo = W1[(j*19 + r)*19 + k0];
            if (m1 < 19) {
                int k1 = (m1 < 12) ? m1 : (m1 < 18 ? m1 + 1 : 12);
                hi = W1[(j*19 + r)*19 + k1];
            }
        }
        sm[OW1 + idx] = pk2(lo, hi);
    }
    for (int idx = tid; idx < 24*20*3; idx += 128) {    // sW2 [j][20 k][3 dp]
        int dp = idx % 3; int t = idx / 3; int k = t % 20; int j = t / 20;
        float lo, hi;
        if (k < 19) { lo = W2[(j*6 + 2*dp)*19 + k]; hi = W2[(j*6 + 2*dp + 1)*19 + k]; }
        else        { lo = b2[j*6 + 2*dp];          hi = b2[j*6 + 2*dp + 1]; }
        sm[OW2 + idx] = pk2(lo, hi);
    }
    for (int idx = tid; idx < 144*6; idx += 128) {      // sW0' [144 kp][6 d]
        int d = idx % 6; int kp = idx / 6;
        int m0 = 2*kp, m1 = 2*kp + 1;
        int J0 = m0/12, i0 = m0%12;
        int f0 = (i0 < 9) ? (9*J0 + i0) : (216 + 3*J0 + (i0 - 9));
        int J1 = m1/12, i1 = m1%12;
        int f1 = (i1 < 9) ? (9*J1 + i1) : (216 + 3*J1 + (i1 - 9));
        sm[OW0 + idx] = pk2(W0[d*288 + f0], W0[d*288 + f1]);
    }
    for (int idx = tid; idx < 24*20; idx += 128) {      // sB1' [j][20 r]
        int r = idx % 20; int j = idx / 20;
        float lo = (r < 19) ? b1[j*19 + r] : 0.f;
        sm[OB1 + idx] = pk2(lo, 0.f);
    }
    if (tid < 6) sm[OB0 + tid] = pk2(b0[tid], 0.f);
    __syncthreads();

    const int p    = tid >> 1;        // pair index: elements 2p, 2p+1
    const int half = tid & 1;         // row/k half
    float* seA = stash + (2*p)     * ESTRIDE;
    float* seB = stash + (2*p + 1) * ESTRIDE;

    // ---- pass 1: gfeat for both elements, shared weight loads ----
    u64t a6A[6], a6B[6];
    if (half == 0) {
#pragma unroll
        for (int d = 0; d < 6; ++d) { a6A[d] = sm[OB0 + d]; a6B[d] = a6A[d]; }
    } else {
#pragma unroll
        for (int d = 0; d < 6; ++d) { a6A[d] = 0ull; a6B[d] = 0ull; }
    }
    {
        const ulonglong2* xqA = (const ulonglong2*)(seA + 144*half);
        const ulonglong2* xqB = (const ulonglong2*)(seB + 144*half);
        const u64t* wbase = sm + OW0 + (72*half)*6;
#pragma unroll 4
        for (int q = 0; q < 36; ++q) {
            ulonglong2 xA = xqA[q], xB = xqB[q];
            const ulonglong2* wp = (const ulonglong2*)(wbase + q*12);
            ulonglong2 w0 = wp[0], w1 = wp[1], w2 = wp[2];
            ulonglong2 w3 = wp[3], w4 = wp[4], w5 = wp[5];
            a6A[0] = fma2(xA.x, w0.x, a6A[0]);  a6B[0] = fma2(xB.x, w0.x, a6B[0]);
            a6A[1] = fma2(xA.x, w0.y, a6A[1]);  a6B[1] = fma2(xB.x, w0.y, a6B[1]);
            a6A[2] = fma2(xA.x, w1.x, a6A[2]);  a6B[2] = fma2(xB.x, w1.x, a6B[2]);
            a6A[3] = fma2(xA.x, w1.y, a6A[3]);  a6B[3] = fma2(xB.x, w1.y, a6B[3]);
            a6A[4] = fma2(xA.x, w2.x, a6A[4]);  a6B[4] = fma2(xB.x, w2.x, a6B[4]);
            a6A[5] = fma2(xA.x, w2.y, a6A[5]);  a6B[5] = fma2(xB.x, w2.y, a6B[5]);
            a6A[0] = fma2(xA.y, w3.x, a6A[0]);  a6B[0] = fma2(xB.y, w3.x, a6B[0]);
            a6A[1] = fma2(xA.y, w3.y, a6A[1]);  a6B[1] = fma2(xB.y, w3.y, a6B[1]);
            a6A[2] = fma2(xA.y, w4.x, a6A[2]);  a6B[2] = fma2(xB.y, w4.x, a6B[2]);
            a6A[3] = fma2(xA.y, w4.y, a6A[3]);  a6B[3] = fma2(xB.y, w4.y, a6B[3]);
            a6A[4] = fma2(xA.y, w5.x, a6A[4]);  a6B[4] = fma2(xB.y, w5.x, a6B[4]);
            a6A[5] = fma2(xA.y, w5.y, a6A[5]);  a6B[5] = fma2(xB.y, w5.y, a6B[5]);
        }
    }
    u64t gA[3], gB[3];
#pragma unroll
    for (int dp = 0; dp < 3; ++dp) {
        float a0, a1, c0, c1;
        unpk(a6A[2*dp],     a0, a1);
        unpk(a6A[2*dp + 1], c0, c1);
        u64t pr = pk2(a0 + a1, c0 + c1);
        gA[dp] = add2(pr, shx1(pr));
        unpk(a6B[2*dp],     a0, a1);
        unpk(a6B[2*dp + 1], c0, c1);
        pr = pk2(a0 + a1, c0 + c1);
        gB[dp] = add2(pr, shx1(pr));
    }

    // ---- pass 2: joint chain, 4-slot register liveness (R10 mapping), dual elements ----
    u64t fA[4][3], fB[4][3];
    float jxA[4], jyA[4], jzA[4], jxB[4], jyB[4], jzB[4];

    do_joint< 0,-1,0>(seA, seB, half, sm, fA, fB, jxA, jyA, jzA, jxB, jyB, jzB, gA, gB);
    do_joint< 1, 0,1>(seA, seB, half, sm, fA, fB, jxA, jyA, jzA, jxB, jyB, jzB, gA, gB);
    do_joint< 2, 0,2>(seA, seB, half, sm, fA, fB, jxA, jyA, jzA, jxB, jyB, jzB, gA, gB);
    do_joint< 3, 0,3>(seA, seB, half, sm, fA, fB, jxA, jyA, jzA, jxB, jyB, jzB, gA, gB);
    do_joint< 4, 1,0>(seA, seB, half, sm, fA, fB, jxA, jyA, jzA, jxB, jyB, jzB, gA, gB);
    do_joint< 5, 2,1>(seA, seB, half, sm, fA, fB, jxA, jyA, jzA, jxB, jyB, jzB, gA, gB);
    do_joint< 6, 3,2>(seA, seB, half, sm, fA, fB, jxA, jyA, jzA, jxB, jyB, jzB, gA, gB);
    do_joint< 7, 0,3>(seA, seB, half, sm, fA, fB, jxA, jyA, jzA, jxB, jyB, jzB, gA, gB);
    do_joint< 8, 1,0>(seA, seB, half, sm, fA, fB, jxA, jyA, jzA, jxB, jyB, jzB, gA, gB);
    do_joint< 9, 2,1>(seA, seB, half, sm, fA, fB, jxA, jyA, jzA, jxB, jyB, jzB, gA, gB);
    do_joint<10, 3,2>(seA, seB, half, sm, fA, fB, jxA, jyA, jzA, jxB, jyB, jzB, gA, gB);
    do_joint<11, 0,2>(seA, seB, half, sm, fA, fB, jxA, jyA, jzA, jxB, jyB, jzB, gA, gB);
    do_joint<12, 1,2>(seA, seB, half, sm, fA, fB, jxA, jyA, jzA, jxB, jyB, jzB, gA, gB);
    do_joint<13, 1,0>(seA, seB, half, sm, fA, fB, jxA, jyA, jzA, jxB, jyB, jzB, gA, gB);
    do_joint<14, 1,3>(seA, seB, half, sm, fA, fB, jxA, jyA, jzA, jxB, jyB, jzB, gA, gB);
    do_joint<15, 2,1>(seA, seB, half, sm, fA, fB, jxA, jyA, jzA, jxB, jyB, jzB, gA, gB);
    do_joint<16, 0,1>(seA, seB, half, sm, fA, fB, jxA, jyA, jzA, jxB, jyB, jzB, gA, gB);
    do_joint<17, 3,0>(seA, seB, half, sm, fA, fB, jxA, jyA, jzA, jxB, jyB, jzB, gA, gB);
    do_joint<18, 1,3>(seA, seB, half, sm, fA, fB, jxA, jyA, jzA, jxB, jyB, jzB, gA, gB);
    do_joint<19, 0,1>(seA, seB, half, sm, fA, fB, jxA, jyA, jzA, jxB, jyB, jzB, gA, gB);
    do_joint<20, 3,0>(seA, seB, half, sm, fA, fB, jxA, jyA, jzA, jxB, jyB, jzB, gA, gB);
    do_joint<21, 1,3>(seA, seB, half, sm, fA, fB, jxA, jyA, jzA, jxB, jyB, jzB, gA, gB);
    do_joint<22, 0,1>(seA, seB, half, sm, fA, fB, jxA, jyA, jzA, jxB, jyB, jzB, gA, gB);
    do_joint<23, 3,0>(seA, seB, half, sm, fA, fB, jxA, jyA, jzA, jxB, jyB, jzB, gA, gB);

    // ---- epilogue: coalesced store of all 128 x 144 outputs ----
    __syncthreads();
    float* og = out + (size_t)blockIdx.x * (128 * 144);
#pragma unroll 8
    for (int i = 0; i < 144; ++i) {
        int G = i*128 + tid;
        int ee = G / 144, q = G % 144;
        int J = q / 6;                                  // f' = q + 6J
        og[G] = stash[ee*ESTRIDE + q + 6*J];
    }
}

extern "C" void kernel_launch(void* const* d_in, const int* in_sizes, int n_in,
                              void* d_out, int out_size) {
    (void)n_in; (void)out_size;
    const float* rots = (const float*)d_in[0];
    const float* jtrs = (const float*)d_in[1];
    const float* W0   = (const float*)d_in[2];
    const float* b0   = (const float*)d_in[3];
    const float* W1   = (const float*)d_in[4];
    const float* b1   = (const float*)d_in[5];
    const float* W2   = (const float*)d_in[6];
    const float* b2   = (const float*)d_in[7];
    float* out = (float*)d_out;

    int n = in_sizes[0] / 216;        // B (131072 -> divisible by 128)
    int grid = n / 128;

    cudaFuncSetAttribute(pose_kernel, cudaFuncAttributeMaxDynamicSharedMemorySize, SMEM_BYTES);
    pose_kernel<<<grid, 128, SMEM_BYTES>>>(rots, jtrs, W0, b0, W1, b1, W2, b2, out);
}

// round 13
// speedup vs baseline: 1.5200x; 1.5200x over previous
#include <cuda_runtime.h>

typedef unsigned long long u64t;

__device__ __forceinline__ u64t fma2(u64t a, u64t b, u64t c) {
    u64t d;
    asm("fma.rn.f32x2 %0, %1, %2, %3;" : "=l"(d) : "l"(a), "l"(b), "l"(c));
    return d;
}
__device__ __forceinline__ u64t add2(u64t a, u64t b) {
    u64t d;
    asm("add.rn.f32x2 %0, %1, %2;" : "=l"(d) : "l"(a), "l"(b));
    return d;
}
__device__ __forceinline__ u64t pk2(float lo, float hi) {
    u64t d;
    asm("mov.b64 %0, {%1, %2};" : "=l"(d) : "f"(lo), "f"(hi));
    return d;
}
__device__ __forceinline__ void unpk(u64t v, float& lo, float& hi) {
    asm("mov.b64 {%0, %1}, %2;" : "=f"(lo), "=f"(hi) : "l"(v));
}
__device__ __forceinline__ float fsqrt_ap(float x) {
    float y;
    asm("sqrt.approx.f32 %0, %1;" : "=f"(y) : "f"(x));
    return y;
}
__device__ __forceinline__ u64t shx1(u64t v) {
    unsigned lo = (unsigned)v, hi = (unsigned)(v >> 32);
    lo = __shfl_xor_sync(0xffffffffu, lo, 1);
    hi = __shfl_xor_sync(0xffffffffu, hi, 1);
    return ((u64t)hi << 32) | lo;
}

// ---- weight region (u64t units), R10 packed layout (sW0 unpermuted) ----
// x-order (new k): [rot 0..8, jtr 9..11, feat 12..17, bone 18, pad 19]
//   old-k map K(m): m<12 -> m ; 12..17 -> m+1 ; 18 -> 12 ; 19 -> zero
// sW1': [24 j][10 kp][20 r]  u64 = (W1[j][r][K(2kp)], W1[j][r][K(2kp+1)])
// sW2 : [24 j][20 k][3 dp]   (k=19 row = b2; fed by hs[9]==1 on odd lane)
// sW0': [144 kp][6 d]        u64 = (W0[d][2kp], W0[d][2kp+1])  (plain feature order)
// sB1': [24 j][20 r]         u64 = (b1, 0)
// sB0': [6 d]                u64 = (b0, 0)
#define OW1 0
#define OW2 4800
#define OW0 6240
#define OB1 7104
#define OB0 7584
#define SM_U64 7590            // 60720 B  (weights ONLY; no stash)
#define SMEM_BYTES (SM_U64 * 8)

template<int J, int PS, int WS>
__device__ __forceinline__ void do_joint(
    const float* __restrict__ re, const float* __restrict__ te,
    float* __restrict__ oe, int half, const u64t* __restrict__ sm,
    u64t (&fslot)[4][3], float (&jx)[4], float (&jy)[4], float (&jz)[4],
    const u64t (&g)[3])
{
    // 12 inputs of joint J via scalar LDG (independent of chain -> hoistable)
    float r0 = re[9*J+0], r1 = re[9*J+1], r2 = re[9*J+2],
          r3 = re[9*J+3], r4 = re[9*J+4], r5 = re[9*J+5],
          r6 = re[9*J+6], r7 = re[9*J+7], r8 = re[9*J+8];
    float j0 = te[3*J+0], j1 = te[3*J+1], j2 = te[3*J+2];

    float dx, dy, dz;
    if (PS < 0) { dx = j0; dy = j1; dz = j2; }
    else {
        const int P = (PS < 0) ? 0 : PS;
        dx = j0 - jx[P]; dy = j1 - jy[P]; dz = j2 - jz[P];
    }
    float bone = fsqrt_ap(dx*dx + dy*dy + dz*dz);
    jx[WS] = j0; jy[WS] = j1; jz[WS] = j2;

    u64t xp[10];
    xp[0] = pk2(r0, r1); xp[1] = pk2(r2, r3); xp[2] = pk2(r4, r5);
    xp[3] = pk2(r6, r7); xp[4] = pk2(r8, j0); xp[5] = pk2(j1, j2);
    if (PS < 0) { xp[6] = g[0]; xp[7] = g[1]; xp[8] = g[2]; }
    else {
        const int P = (PS < 0) ? 0 : PS;
        xp[6] = fslot[P][0]; xp[7] = fslot[P][1]; xp[8] = fslot[P][2];
    }
    xp[9] = pk2(bone, bone);             // hi weight is 0

    // ---- layer 1: 10 rows (this half), acc = (even-kp, odd-kp) partials ----
    u64t acc[10];
    {
        const ulonglong2* bb = (const ulonglong2*)(sm + OB1 + J*20 + 10*half);
        ulonglong2 c0 = bb[0], c1 = bb[1], c2 = bb[2], c3 = bb[3], c4 = bb[4];
        acc[0]=c0.x; acc[1]=c0.y; acc[2]=c1.x; acc[3]=c1.y; acc[4]=c2.x;
        acc[5]=c2.y; acc[6]=c3.x; acc[7]=c3.y; acc[8]=c4.x; acc[9]=c4.y;
    }
    const u64t* wb = sm + OW1 + (J*10)*20 + 10*half;
#pragma unroll
    for (int i = 0; i < 10; ++i) {
        const ulonglong2* wr = (const ulonglong2*)(wb + i*20);
        ulonglong2 wa = wr[0], wc = wr[1], wd = wr[2], we = wr[3], wf = wr[4];
        u64t xx = xp[i];
        acc[0] = fma2(xx, wa.x, acc[0]);
        acc[1] = fma2(xx, wa.y, acc[1]);
        acc[2] = fma2(xx, wc.x, acc[2]);
        acc[3] = fma2(xx, wc.y, acc[3]);
        acc[4] = fma2(xx, wd.x, acc[4]);
        acc[5] = fma2(xx, wd.y, acc[5]);
        acc[6] = fma2(xx, we.x, acc[6]);
        acc[7] = fma2(xx, we.y, acc[7]);
        acc[8] = fma2(xx, wf.x, acc[8]);
        acc[9] = fma2(xx, wf.y, acc[9]);
    }

    // combine even/odd-kp partials + relu
    float hs[10];
#pragma unroll
    for (int r = 0; r < 10; ++r) {
        float a, b; unpk(acc[r], a, b);
        hs[r] = fmaxf(a + b, 0.f);
    }
    if (half) hs[9] = 1.0f;              // global row 19 -> feeds b2 row (k=19)

    // ---- layer 2: preload 30 contiguous u64 weights, FMA burst ----
    ulonglong2 wz[15];
    {
        const ulonglong2* wp = (const ulonglong2*)(sm + OW2 + (J*20 + 10*half)*3);
#pragma unroll
        for (int i = 0; i < 15; ++i) wz[i] = wp[i];
    }
    u64t o0 = 0ull, o1 = 0ull, o2 = 0ull;
#pragma unroll
    for (int i = 0; i < 5; ++i) {
        u64t x0 = pk2(hs[2*i],   hs[2*i]);
        u64t x1 = pk2(hs[2*i+1], hs[2*i+1]);
        o0 = fma2(x0, wz[3*i  ].x, o0);
        o1 = fma2(x0, wz[3*i  ].y, o1);
        o2 = fma2(x0, wz[3*i+1].x, o2);
        o0 = fma2(x1, wz[3*i+1].y, o0);
        o1 = fma2(x1, wz[3*i+2].x, o1);
        o2 = fma2(x1, wz[3*i+2].y, o2);
    }
    o0 = add2(o0, shx1(o0));
    o1 = add2(o1, shx1(o1));
    o2 = add2(o2, shx1(o2));

    fslot[WS][0] = o0; fslot[WS][1] = o1; fslot[WS][2] = o2;

    // direct global store: 8B-aligned (e*576 + 24J bytes)
    u64t* d = (u64t*)(oe + 6*J);
    if (half == 0) { d[0] = o0; d[1] = o1; }
    else           { d[2] = o2; }
}

__global__ void __launch_bounds__(512, 1)
pose_kernel(const float* __restrict__ rots, const float* __restrict__ jtrs,
            const float* __restrict__ W0, const float* __restrict__ b0,
            const float* __restrict__ W1, const float* __restrict__ b1,
            const float* __restrict__ W2, const float* __restrict__ b2,
            float* __restrict__ out)
{
    extern __shared__ u64t sm[];
    const int tid = threadIdx.x;

    // ---- weight packing (R10 layout; sW0 unpermuted) ----
    for (int idx = tid; idx < 24*10*20; idx += 512) {   // sW1' [j][kp][20 r]
        int r = idx % 20; int t = idx / 20; int i = t % 10; int j = t / 10;
        int m0 = 2*i, m1 = 2*i + 1;
        float lo = 0.f, hi = 0.f;
        if (r < 19) {
            int k0 = (m0 < 12) ? m0 : (m0 < 18 ? m0 + 1 : 12);
            lo = W1[(j*19 + r)*19 + k0];
            if (m1 < 19) {
                int k1 = (m1 < 12) ? m1 : (m1 < 18 ? m1 + 1 : 12);
                hi = W1[(j*19 + r)*19 + k1];
            }
        }
        sm[OW1 + idx] = pk2(lo, hi);
    }
    for (int idx = tid; idx < 24*20*3; idx += 512) {    // sW2 [j][20 k][3 dp]
        int dp = idx % 3; int t = idx / 3; int k = t % 20; int j = t / 20;
        float lo, hi;
        if (k < 19) { lo = W2[(j*6 + 2*dp)*19 + k]; hi = W2[(j*6 + 2*dp + 1)*19 + k]; }
        else        { lo = b2[j*6 + 2*dp];          hi = b2[j*6 + 2*dp + 1]; }
        sm[OW2 + idx] = pk2(lo, hi);
    }
    for (int idx = tid; idx < 144*6; idx += 512) {      // sW0' [144 kp][6 d]
        int d = idx % 6; int kp = idx / 6;
        sm[OW0 + idx] = pk2(W0[d*288 + 2*kp], W0[d*288 + 2*kp + 1]);
    }
    for (int idx = tid; idx < 24*20; idx += 512) {      // sB1' [j][20 r]
        int r = idx % 20; int j = idx / 20;
        float lo = (r < 19) ? b1[j*19 + r] : 0.f;
        sm[OB1 + idx] = pk2(lo, 0.f);
    }
    if (tid < 6) sm[OB0 + tid] = pk2(b0[tid], 0.f);
    __syncthreads();

    const int p    = tid >> 1;          // element within CTA block
    const int half = tid & 1;           // row/k half
    size_t e = (size_t)blockIdx.x * 256 + p;

    const float* re = rots + e * 216;
    const float* te = jtrs + e * 72;
    float*       oe = out  + e * 144;

    // ---- pass 1: gfeat partial over this lane's feature half (direct LDG.128) ----
    u64t a6[6];
    if (half == 0) {
#pragma unroll
        for (int d = 0; d < 6; ++d) a6[d] = sm[OB0 + d];
    } else {
#pragma unroll
        for (int d = 0; d < 6; ++d) a6[d] = 0ull;
    }
    {
        // half 0: features   0..143 -> re[0..72) , re[72..144)
        // half 1: features 144..287 -> re[144..216), te[0..72)
        const float4* s0 = (half == 0) ? (const float4*)re        : (const float4*)(re + 144);
        const float4* s1 = (half == 0) ? (const float4*)(re + 72) : (const float4*)te;
        const u64t* wbase = sm + OW0 + (72*half)*6;
#pragma unroll 4
        for (int q = 0; q < 36; ++q) {
            float4 xv4 = (q < 18) ? s0[q] : s1[q - 18];
            u64t xlo = pk2(xv4.x, xv4.y);        // kp 2q
            u64t xhi = pk2(xv4.z, xv4.w);        // kp 2q+1
            const ulonglong2* wp = (const ulonglong2*)(wbase + q*12);
            ulonglong2 w0 = wp[0], w1 = wp[1], w2 = wp[2];
            ulonglong2 w3 = wp[3], w4 = wp[4], w5 = wp[5];
            a6[0] = fma2(xlo, w0.x, a6[0]);
            a6[1] = fma2(xlo, w0.y, a6[1]);
            a6[2] = fma2(xlo, w1.x, a6[2]);
            a6[3] = fma2(xlo, w1.y, a6[3]);
            a6[4] = fma2(xlo, w2.x, a6[4]);
            a6[5] = fma2(xlo, w2.y, a6[5]);
            a6[0] = fma2(xhi, w3.x, a6[0]);
            a6[1] = fma2(xhi, w3.y, a6[1]);
            a6[2] = fma2(xhi, w4.x, a6[2]);
            a6[3] = fma2(xhi, w4.y, a6[3]);
            a6[4] = fma2(xhi, w5.x, a6[4]);
            a6[5] = fma2(xhi, w5.y, a6[5]);
        }
    }
    u64t g[3];
#pragma unroll
    for (int dp = 0; dp < 3; ++dp) {
        float a0, a1, c0, c1;
        unpk(a6[2*dp],     a0, a1);
        unpk(a6[2*dp + 1], c0, c1);
        u64t pr = pk2(a0 + a1, c0 + c1);
        g[dp] = add2(pr, shx1(pr));
    }

    // ---- pass 2: joint chain, 4-slot register liveness (proven R9/R10 mapping) ----
    u64t fslot[4][3];
    float jx[4], jy[4], jz[4];

    do_joint< 0,-1,0>(re, te, oe, half, sm, fslot, jx, jy, jz, g);
    do_joint< 1, 0,1>(re, te, oe, half, sm, fslot, jx, jy, jz, g);
    do_joint< 2, 0,2>(re, te, oe, half, sm, fslot, jx, jy, jz, g);
    do_joint< 3, 0,3>(re, te, oe, half, sm, fslot, jx, jy, jz, g);
    do_joint< 4, 1,0>(re, te, oe, half, sm, fslot, jx, jy, jz, g);
    do_joint< 5, 2,1>(re, te, oe, half, sm, fslot, jx, jy, jz, g);
    do_joint< 6, 3,2>(re, te, oe, half, sm, fslot, jx, jy, jz, g);
    do_joint< 7, 0,3>(re, te, oe, half, sm, fslot, jx, jy, jz, g);
    do_joint< 8, 1,0>(re, te, oe, half, sm, fslot, jx, jy, jz, g);
    do_joint< 9, 2,1>(re, te, oe, half, sm, fslot, jx, jy, jz, g);
    do_joint<10, 3,2>(re, te, oe, half, sm, fslot, jx, jy, jz, g);
    do_joint<11, 0,2>(re, te, oe, half, sm, fslot, jx, jy, jz, g);
    do_joint<12, 1,2>(re, te, oe, half, sm, fslot, jx, jy, jz, g);
    do_joint<13, 1,0>(re, te, oe, half, sm, fslot, jx, jy, jz, g);
    do_joint<14, 1,3>(re, te, oe, half, sm, fslot, jx, jy, jz, g);
    do_joint<15, 2,1>(re, te, oe, half, sm, fslot, jx, jy, jz, g);
    do_joint<16, 0,1>(re, te, oe, half, sm, fslot, jx, jy, jz, g);
    do_joint<17, 3,0>(re, te, oe, half, sm, fslot, jx, jy, jz, g);
    do_joint<18, 1,3>(re, te, oe, half, sm, fslot, jx, jy, jz, g);
    do_joint<19, 0,1>(re, te, oe, half, sm, fslot, jx, jy, jz, g);
    do_joint<20, 3,0>(re, te, oe, half, sm, fslot, jx, jy, jz, g);
    do_joint<21, 1,3>(re, te, oe, half, sm, fslot, jx, jy, jz, g);
    do_joint<22, 0,1>(re, te, oe, half, sm, fslot, jx, jy, jz, g);
    do_joint<23, 3,0>(re, te, oe, half, sm, fslot, jx, jy, jz, g);
}

extern "C" void kernel_launch(void* const* d_in, const int* in_sizes, int n_in,
                              void* d_out, int out_size) {
    (void)n_in; (void)out_size;
    const float* rots = (const float*)d_in[0];
    const float* jtrs = (const float*)d_in[1];
    const float* W0   = (const float*)d_in[2];
    const float* b0   = (const float*)d_in[3];
    const float* W1   = (const float*)d_in[4];
    const float* b1   = (const float*)d_in[5];
    const float* W2   = (const float*)d_in[6];
    const float* b2   = (const float*)d_in[7];
    float* out = (float*)d_out;

    int n = in_sizes[0] / 216;        // B (131072 -> divisible by 256)
    int grid = n / 256;

    cudaFuncSetAttribute(pose_kernel, cudaFuncAttributeMaxDynamicSharedMemorySize, SMEM_BYTES);
    pose_kernel<<<grid, 512, SMEM_BYTES>>>(rots, jtrs, W0, b0, W1, b1, W2, b2, out);
}